// round 1
// baseline (speedup 1.0000x reference)
#include <cuda_runtime.h>

// Density loss: for each of 2 point clouds [8, 2048, 3], per-point mean of the
// 16 smallest squared pairwise distances (self included), mean over points,
// then MSE between the two per-batch scalars.

#define B 8
#define N 2048
#define KNN 16
#define THREADS 128
#define CHUNKS (N / THREADS)          // 16 chunks of 128 points
#define BLOCKS_PER_TENSOR (B * CHUNKS) // 128
#define TOTAL_BLOCKS (2 * BLOCKS_PER_TENSOR) // 256

__device__ float g_partial[TOTAL_BLOCKS];

__global__ __launch_bounds__(THREADS)
void knn_density_kernel(const float* __restrict__ seed,
                        const float* __restrict__ gt_s) {
    __shared__ float4 pts[N];        // (x, y, z, |p|^2)
    __shared__ float red[THREADS];

    const int bx     = blockIdx.x;
    const int chunk  = bx % CHUNKS;
    const int batch  = (bx / CHUNKS) % B;
    const int tensor = bx / BLOCKS_PER_TENSOR;
    const int tid    = threadIdx.x;

    const float* __restrict__ src =
        (tensor == 0 ? seed : gt_s) + (size_t)batch * N * 3;

    // Load this batch's cloud into shared memory with precomputed |p|^2.
    for (int p = tid; p < N; p += THREADS) {
        float x = src[3 * p + 0];
        float y = src[3 * p + 1];
        float z = src[3 * p + 2];
        pts[p] = make_float4(x, y, z, x * x + y * y + z * z);
    }
    __syncthreads();

    // My point.
    const int myp = chunk * THREADS + tid;
    const float4 xi = pts[myp];
    const float ai = xi.w;          // |xi|^2
    const float mx = -2.0f * xi.x;
    const float my = -2.0f * xi.y;
    const float mz = -2.0f * xi.z;

    // Sorted ascending register array of the 16 smallest distances seen.
    float arr[KNN];
#pragma unroll
    for (int j = 0; j < KNN; ++j) arr[j] = 3.4e38f;

#pragma unroll 4
    for (int j = 0; j < N; ++j) {
        float4 s = pts[j];          // warp-broadcast LDS.128
        // d = |xi|^2 + |xj|^2 - 2 xi.xj  (same form as the reference)
        float d = ai + s.w;
        d = fmaf(mx, s.x, d);
        d = fmaf(my, s.y, d);
        d = fmaf(mz, s.z, d);
        if (d < arr[KNN - 1]) {
            // One insertion pass: keeps arr sorted ascending, evicts the max.
            float x = d;
#pragma unroll
            for (int q = 0; q < KNN; ++q) {
                float mn = fminf(x, arr[q]);
                float mxv = fmaxf(x, arr[q]);
                arr[q] = mn;
                x = mxv;
            }
        }
    }

    // Per-point mean of the 16 nearest distances.
    float s16 = 0.0f;
#pragma unroll
    for (int j = 0; j < KNN; ++j) s16 += arr[j];
    float point_mean = s16 * (1.0f / KNN);

    // Block reduction (deterministic tree).
    red[tid] = point_mean;
    __syncthreads();
#pragma unroll
    for (int stride = THREADS / 2; stride > 0; stride >>= 1) {
        if (tid < stride) red[tid] += red[tid + stride];
        __syncthreads();
    }
    if (tid == 0) g_partial[bx] = red[0];
}

__global__ void finalize_kernel(float* __restrict__ out) {
    if (threadIdx.x == 0) {
        float dis[2][B];
#pragma unroll
        for (int t = 0; t < 2; ++t) {
#pragma unroll
            for (int b = 0; b < B; ++b) {
                float s = 0.0f;
#pragma unroll
                for (int c = 0; c < CHUNKS; ++c)
                    s += g_partial[t * BLOCKS_PER_TENSOR + b * CHUNKS + c];
                dis[t][b] = s * (1.0f / N);
            }
        }
        float loss = 0.0f;
#pragma unroll
        for (int b = 0; b < B; ++b) {
            float df = dis[0][b] - dis[1][b];
            loss += df * df;
        }
        out[0] = loss * (1.0f / B);
    }
}

extern "C" void kernel_launch(void* const* d_in, const int* in_sizes, int n_in,
                              void* d_out, int out_size) {
    const float* seed = (const float*)d_in[0];
    const float* gt_s = (const float*)d_in[1];
    float* out = (float*)d_out;

    knn_density_kernel<<<TOTAL_BLOCKS, THREADS>>>(seed, gt_s);
    finalize_kernel<<<1, 32>>>(out);
}

// round 3
// speedup vs baseline: 1.7976x; 1.7976x over previous
#include <cuda_runtime.h>

// Density loss: for each of 2 point clouds [8, 2048, 3], per-point mean of the
// 16 smallest squared pairwise distances (self included), mean over points,
// then MSE between the two per-batch scalars.
//
// Branchless top-16: candidates processed in batches of 16 per thread.
// Each batch is sorted with Batcher's odd-even mergesort (63 CE), merged
// against the running sorted top-16 via the bitonic-merge min step, then the
// (bitonic) result is cleaned up with a 32-CE bitonic sort. No divergence.

#define B 8
#define N 2048
#define KNN 16
#define THREADS 256
#define PTS_PER_BLOCK THREADS
#define SEGS (N / PTS_PER_BLOCK)            // 8 segments of 256 points
#define BLOCKS_PER_TENSOR (B * SEGS)        // 64
#define TOTAL_BLOCKS (2 * BLOCKS_PER_TENSOR) // 128

__device__ float g_partial[TOTAL_BLOCKS];

// compare-exchange: x <- min, y <- max
#define CE(x, y) { float _lo = fminf((x), (y)); (y) = fmaxf((x), (y)); (x) = _lo; }

__global__ __launch_bounds__(THREADS)
void knn_density_kernel(const float* __restrict__ seed,
                        const float* __restrict__ gt_s) {
    __shared__ float4 pts[N];        // (x, y, z, |p|^2)
    __shared__ float red[THREADS];

    const int bx     = blockIdx.x;
    const int seg    = bx % SEGS;
    const int batch  = (bx / SEGS) % B;
    const int tensor = bx / BLOCKS_PER_TENSOR;
    const int tid    = threadIdx.x;

    const float* __restrict__ src =
        (tensor == 0 ? seed : gt_s) + (size_t)batch * N * 3;

    // Load this batch's cloud into shared memory with precomputed |p|^2.
    for (int p = tid; p < N; p += THREADS) {
        float x = src[3 * p + 0];
        float y = src[3 * p + 1];
        float z = src[3 * p + 2];
        pts[p] = make_float4(x, y, z, x * x + y * y + z * z);
    }
    __syncthreads();

    // My point.
    const int myp = seg * PTS_PER_BLOCK + tid;
    const float4 xi = pts[myp];
    const float ai = xi.w;          // |xi|^2
    const float mx = -2.0f * xi.x;
    const float my = -2.0f * xi.y;
    const float mz = -2.0f * xi.z;

    // Running sorted (ascending) top-16.
    float a[KNN];
#pragma unroll
    for (int j = 0; j < KNN; ++j) a[j] = 3.4e38f;

    for (int base = 0; base < N; base += 16) {
        float c[16];
#pragma unroll
        for (int q = 0; q < 16; ++q) {
            float4 s = pts[base + q];            // warp-broadcast LDS.128
            float d = ai + s.w;                  // |xi|^2 + |xj|^2
            d = fmaf(mx, s.x, d);
            d = fmaf(my, s.y, d);
            d = fmaf(mz, s.z, d);
            c[q] = d;
        }

        // ---- Batcher odd-even mergesort, 16 inputs, 63 CE, ascending ----
        // sort4 (0-3)
        CE(c[0], c[1]) CE(c[2], c[3]) CE(c[0], c[2]) CE(c[1], c[3]) CE(c[1], c[2])
        // sort4 (4-7)
        CE(c[4], c[5]) CE(c[6], c[7]) CE(c[4], c[6]) CE(c[5], c[7]) CE(c[5], c[6])
        // merge8 (0-7)
        CE(c[0], c[4]) CE(c[2], c[6]) CE(c[2], c[4])
        CE(c[1], c[5]) CE(c[3], c[7]) CE(c[3], c[5])
        CE(c[1], c[2]) CE(c[3], c[4]) CE(c[5], c[6])
        // sort4 (8-11)
        CE(c[8], c[9]) CE(c[10], c[11]) CE(c[8], c[10]) CE(c[9], c[11]) CE(c[9], c[10])
        // sort4 (12-15)
        CE(c[12], c[13]) CE(c[14], c[15]) CE(c[12], c[14]) CE(c[13], c[15]) CE(c[13], c[14])
        // merge8 (8-15)
        CE(c[8], c[12]) CE(c[10], c[14]) CE(c[10], c[12])
        CE(c[9], c[13]) CE(c[11], c[15]) CE(c[11], c[13])
        CE(c[9], c[10]) CE(c[11], c[12]) CE(c[13], c[14])
        // merge16: evens chain
        CE(c[0], c[8])  CE(c[4], c[12]) CE(c[4], c[8])
        CE(c[2], c[10]) CE(c[6], c[14]) CE(c[6], c[10])
        CE(c[2], c[4])  CE(c[6], c[8])  CE(c[10], c[12])
        // merge16: odds chain
        CE(c[1], c[9])  CE(c[5], c[13]) CE(c[5], c[9])
        CE(c[3], c[11]) CE(c[7], c[15]) CE(c[7], c[11])
        CE(c[3], c[5])  CE(c[7], c[9])  CE(c[11], c[13])
        // merge16: final layer
        CE(c[1], c[2]) CE(c[3], c[4]) CE(c[5], c[6]) CE(c[7], c[8])
        CE(c[9], c[10]) CE(c[11], c[12]) CE(c[13], c[14])

        // ---- keep lowest 16 of (a asc, c asc): bitonic-merge min step ----
#pragma unroll
        for (int q = 0; q < 16; ++q) a[q] = fminf(a[q], c[15 - q]);

        // ---- a is now bitonic: clean up with 4-stage bitonic sort (32 CE) ----
#pragma unroll
        for (int q = 0; q < 8; ++q) CE(a[q], a[q + 8])
        CE(a[0], a[4]) CE(a[1], a[5]) CE(a[2], a[6]) CE(a[3], a[7])
        CE(a[8], a[12]) CE(a[9], a[13]) CE(a[10], a[14]) CE(a[11], a[15])
        CE(a[0], a[2]) CE(a[1], a[3]) CE(a[4], a[6]) CE(a[5], a[7])
        CE(a[8], a[10]) CE(a[9], a[11]) CE(a[12], a[14]) CE(a[13], a[15])
        CE(a[0], a[1]) CE(a[2], a[3]) CE(a[4], a[5]) CE(a[6], a[7])
        CE(a[8], a[9]) CE(a[10], a[11]) CE(a[12], a[13]) CE(a[14], a[15])
    }

    // Per-point mean of the 16 nearest distances.
    float s16 = 0.0f;
#pragma unroll
    for (int j = 0; j < KNN; ++j) s16 += a[j];
    float point_mean = s16 * (1.0f / KNN);

    // Block reduction (deterministic tree).
    red[tid] = point_mean;
    __syncthreads();
#pragma unroll
    for (int stride = THREADS / 2; stride > 0; stride >>= 1) {
        if (tid < stride) red[tid] += red[tid + stride];
        __syncthreads();
    }
    if (tid == 0) g_partial[bx] = red[0];
}

__global__ __launch_bounds__(TOTAL_BLOCKS)
void finalize_kernel(float* __restrict__ out) {
    __shared__ float s[TOTAL_BLOCKS];
    __shared__ float dd[2 * B];
    const int tid = threadIdx.x;

    s[tid] = g_partial[tid];
    __syncthreads();

    if (tid < 2 * B) {
        float acc = 0.0f;
#pragma unroll
        for (int c = 0; c < SEGS; ++c) acc += s[tid * SEGS + c];
        dd[tid] = acc * (1.0f / N);
    }
    __syncthreads();

    if (tid == 0) {
        float loss = 0.0f;
#pragma unroll
        for (int b = 0; b < B; ++b) {
            float df = dd[b] - dd[B + b];
            loss += df * df;
        }
        out[0] = loss * (1.0f / B);
    }
}

extern "C" void kernel_launch(void* const* d_in, const int* in_sizes, int n_in,
                              void* d_out, int out_size) {
    const float* seed = (const float*)d_in[0];
    const float* gt_s = (const float*)d_in[1];
    float* out = (float*)d_out;

    knn_density_kernel<<<TOTAL_BLOCKS, THREADS>>>(seed, gt_s);
    finalize_kernel<<<1, TOTAL_BLOCKS>>>(out);
}